// round 14
// baseline (speedup 1.0000x reference)
#include <cuda_runtime.h>
#include <cstdint>

#define NTOK   8192
#define NEXP   16
#define CAP    512
#define FDIM   512
#define IDIM   1024
#define TI3    3072
#define SEQ    2048

#define OFF_XIN   0u
#define OFF_BIG   4194304u
#define OFF_TN1   29360128u
#define OFF_TN2   37748736u
#define OFF_Y2    46137344u
#define OFF_GATES 50331648u
#define OFF_SCALE 50462720u
#define OFF_AG    50470912u
#define OFF_W0D   58859520u
#define OFF_W1TD  109191168u
#define OFF_W2D   128065536u
#define SCRATCH_FLOATS 144842752u

__device__ float g_scratch[SCRATCH_FLOATS];
__device__ int   g_iscr[131072 + 8192];   // ord | perm

__device__ __forceinline__ uint32_t s2u(const void* p) {
    uint32_t r;
    asm("{ .reg .u64 t; cvta.to.shared.u64 t, %1; cvt.u32.u64 %0, t; }" : "=r"(r) : "l"(p));
    return r;
}
__device__ __forceinline__ void cpasync16(uint32_t dst, const void* src) {
    asm volatile("cp.async.cg.shared.global [%0], [%1], 16;" :: "r"(dst), "l"(src));
}
#define CP_COMMIT() asm volatile("cp.async.commit_group;" ::: "memory")
#define CP_WAIT0()  asm volatile("cp.async.wait_group 0;" ::: "memory")

__device__ __forceinline__ void upk2(unsigned long long v, float& lo, float& hi) {
    asm("mov.b64 {%0, %1}, %2;" : "=f"(lo), "=f"(hi) : "l"(v));
}
__device__ __forceinline__ void fma2(unsigned long long& d, unsigned long long a,
                                     unsigned long long b) {
    asm("fma.rn.f32x2 %0, %1, %2, %0;" : "+l"(d) : "l"(a), "l"(b));
}

// ---------------- transposes ----------------
__global__ void k_transpose_in(const float* __restrict__ in, float* __restrict__ out) {
    __shared__ float tile[32][33];
    int b = blockIdx.z, s0 = blockIdx.x * 32, f0 = blockIdx.y * 32;
    int tx = threadIdx.x, ty = threadIdx.y;
    #pragma unroll
    for (int r = ty; r < 32; r += 8)
        tile[r][tx] = in[((size_t)(b * FDIM + f0 + r)) * SEQ + s0 + tx];
    __syncthreads();
    #pragma unroll
    for (int r = ty; r < 32; r += 8)
        out[((size_t)(b * SEQ + s0 + r)) * FDIM + f0 + tx] = tile[tx][r];
}

__global__ void k_transpose_out(const float* __restrict__ y2, float* __restrict__ out) {
    __shared__ float tile[32][33];
    int b = blockIdx.z, s0 = blockIdx.x * 32, f0 = blockIdx.y * 32;
    int tx = threadIdx.x, ty = threadIdx.y;
    #pragma unroll
    for (int r = ty; r < 32; r += 8)
        tile[r][tx] = y2[((size_t)(b * SEQ + s0 + r)) * FDIM + f0 + tx];
    __syncthreads();
    #pragma unroll
    for (int r = ty; r < 32; r += 8)
        out[((size_t)(b * FDIM + f0 + r)) * SEQ + s0 + tx] = tile[tx][r];
}

// w1 [O][I][k] -> duplicated w1td [k*1024+i][2o] = [..][2o+1]
__global__ void k_w1t(const float* __restrict__ w1, float* __restrict__ w1td) {
    __shared__ float tile[32][33];
    int k = blockIdx.z, o0 = blockIdx.x * 32, i0 = blockIdx.y * 32;
    int tx = threadIdx.x, ty = threadIdx.y;
    #pragma unroll
    for (int r = ty; r < 32; r += 8)
        tile[r][tx] = w1[((size_t)(o0 + r) * IDIM + i0 + tx) * 3 + k];
    __syncthreads();
    #pragma unroll
    for (int r = ty; r < 32; r += 8) {
        float v = tile[tx][r];
        *(float2*)(w1td + ((size_t)k * IDIM + i0 + r) * (2 * TI3) + 2 * (o0 + tx)) =
            make_float2(v, v);
    }
}

// generic element duplication: dst[2i]=dst[2i+1]=src[i]  (row-major dup preserved)
__global__ void k_dup(const float* __restrict__ src, float* __restrict__ dst) {
    size_t i = (size_t)blockIdx.x * 256 + threadIdx.x;
    float v = src[i];
    *(float2*)(dst + 2 * i) = make_float2(v, v);
}

// ---------------- gate logits + softmax ----------------
__global__ __launch_bounds__(256) void k_logits(const float* __restrict__ X,
                                                const float* __restrict__ G,
                                                float* __restrict__ gates, int K) {
    __shared__ float Xs[16][65];
    __shared__ float Gs[64][16];
    int t0 = blockIdx.x * 16, tid = threadIdx.x;
    int e = tid & 15, tl = tid >> 4;
    float acc = 0.f;
    for (int k0 = 0; k0 < K; k0 += 64) {
        __syncthreads();
        #pragma unroll
        for (int r = 0; r < 4; r++) {
            int j = tid + 256 * r;
            Xs[j >> 6][j & 63] = X[(size_t)(t0 + (j >> 6)) * K + k0 + (j & 63)];
        }
        #pragma unroll
        for (int r = 0; r < 4; r++) {
            int j = tid + 256 * r;
            Gs[j >> 4][j & 15] = G[(size_t)(k0 + (j >> 4)) * NEXP + (j & 15)];
        }
        __syncthreads();
        #pragma unroll
        for (int k = 0; k < 64; k++) acc += Xs[tl][k] * Gs[k][e];
    }
    float m = acc;
    #pragma unroll
    for (int o = 8; o >= 1; o >>= 1) m = fmaxf(m, __shfl_xor_sync(0xffffffffu, m, o, 16));
    float ex = expf(acc - m);
    float s = ex;
    #pragma unroll
    for (int o = 8; o >= 1; o >>= 1) s += __shfl_xor_sync(0xffffffffu, s, o, 16);
    gates[(size_t)(t0 + tl) * NEXP + e] = ex / s;
}

// ---------------- per-expert descending sort ----------------
__global__ __launch_bounds__(1024) void k_sort(const float* __restrict__ gates,
                                               int* __restrict__ ord) {
    extern __shared__ unsigned long long smsort[];
    int e = blockIdx.x, tid = threadIdx.x;
    #pragma unroll
    for (int r = 0; r < 8; r++) {
        int i = r * 1024 + tid;
        unsigned fb = __float_as_uint(gates[(size_t)i * NEXP + e]);
        smsort[i] = ((unsigned long long)fb << 32) | (unsigned)(NTOK - 1 - i);
    }
    __syncthreads();
    for (int k = 2; k <= NTOK; k <<= 1) {
        for (int j = k >> 1; j > 0; j >>= 1) {
            #pragma unroll
            for (int r = 0; r < 8; r++) {
                int i = r * 1024 + tid;
                int l = i ^ j;
                if (l > i) {
                    unsigned long long a = smsort[i], b = smsort[l];
                    bool desc = ((i & k) == 0);
                    if ((a < b) == desc) { smsort[i] = b; smsort[l] = a; }
                }
            }
            __syncthreads();
        }
    }
    #pragma unroll
    for (int r = 0; r < 8; r++) {
        int i = r * 1024 + tid;
        ord[e * NTOK + i] = NTOK - 1 - (int)(unsigned)(smsort[i] & 0xffffffffu);
    }
}

// ---------------- greedy capacity assignment ----------------
__global__ __launch_bounds__(1024) void k_greedy(const int* __restrict__ ord,
                                                 int* __restrict__ perm) {
    __shared__ unsigned assigned[NTOK / 32];
    __shared__ int wsums[32];
    int tid = threadIdx.x, lane = tid & 31, wid = tid >> 5;
    if (tid < NTOK / 32) assigned[tid] = 0u;
    __syncthreads();
    for (int e = 0; e < NEXP; e++) {
        int toks[8];
        int flags = 0, cnt = 0;
        #pragma unroll
        for (int i = 0; i < 8; i++) {
            int tok = ord[e * NTOK + tid * 8 + i];
            toks[i] = tok;
            bool freetok = !((assigned[tok >> 5] >> (tok & 31)) & 1u);
            flags |= ((int)freetok) << i;
            cnt += (int)freetok;
        }
        int v = cnt;
        #pragma unroll
        for (int o = 1; o < 32; o <<= 1) {
            int n = __shfl_up_sync(0xffffffffu, v, o);
            if (lane >= o) v += n;
        }
        if (lane == 31) wsums[wid] = v;
        __syncthreads();
        if (wid == 0) {
            int w = wsums[lane];
            #pragma unroll
            for (int o = 1; o < 32; o <<= 1) {
                int n = __shfl_up_sync(0xffffffffu, w, o);
                if (lane >= o) w += n;
            }
            wsums[lane] = w;
        }
        __syncthreads();
        int r = v - cnt + (wid ? wsums[wid - 1] : 0);
        #pragma unroll
        for (int i = 0; i < 8; i++) {
            if ((flags >> i) & 1) {
                if (r < CAP) {
                    int tok = toks[i];
                    perm[r * NEXP + e] = tok;
                    atomicOr(&assigned[tok >> 5], 1u << (tok & 31));
                }
                r++;
            }
        }
        __syncthreads();
    }
}

__global__ void k_scale(const int* __restrict__ perm, const float* __restrict__ gates,
                        float* __restrict__ scl) {
    int p = blockIdx.x * 256 + threadIdx.x;
    int tok = perm[p];
    scl[tok] = gates[(size_t)tok * NEXP + (p >> 9)];
}

__global__ void k_fgather(const float* __restrict__ X, const int* __restrict__ perm,
                          const float* __restrict__ scl, float* __restrict__ Ag, int K) {
    int col = blockIdx.x * 256 + threadIdx.x;
    int q = blockIdx.y;
    int tok = perm[(q & 511) * NEXP + (q >> 9)];
    Ag[(size_t)q * K + col] = X[(size_t)tok * K + col] * scl[tok];
}

// ===== fp32 GEMM, f32x2; A alias-packed, B pre-duplicated (zero packing movs) =====
#define KC 16
#define GEMM_SMEM ((2 * KC * 128 + 2 * KC * 256 + 128) * 4)

__global__ __launch_bounds__(256, 2) void k_gemm_f32(
    const float* __restrict__ A, const float* __restrict__ Bd,
    const int* __restrict__ perm, float* __restrict__ Y,
    int N, int K, int aStride, int isConv)
{
    extern __shared__ float dsm[];
    float* AsP = dsm;                        // [2][KC][128]
    float* BsP = dsm + 2 * KC * 128;         // [2][KC][256] duplicated
    int*  stok = (int*)(BsP + 2 * KC * 256);

    int tid = threadIdx.x;
    int e = blockIdx.z, n0 = blockIdx.x * 128, by = blockIdx.y;
    int m0 = isConv ? by * 128 : e * CAP + by * 128;
    if (tid < 128) stok[tid] = perm ? perm[(by * 128 + tid) * NEXP + e] : (m0 + tid);

    const float* Bb = Bd + (size_t)e * K * 2 * N;   // dup row stride = 2N
    int tx = tid & 15, ty = tid >> 4;
    int rowA = tid >> 2, seg = (tid & 3) * 4;
    int bK = tid >> 4, bC16 = (tid & 15) * 16;
    uint32_t bs = s2u(BsP);

    unsigned long long acc2[4][8];
    #pragma unroll
    for (int i = 0; i < 4; i++)
        #pragma unroll
        for (int j = 0; j < 8; j++) acc2[i][j] = 0ull;

    float4 ra0, ra1;
    int L = K / KC;

    #define LOADA(c) do {                                                              \
        int kc = (c) * KC;                                                             \
        if (!isConv) {                                                                 \
            ra0 = *(const float4*)(A + (size_t)(m0 + rowA) * aStride + kc + seg);      \
            ra1 = *(const float4*)(A + (size_t)(m0 + 64 + rowA) * aStride + kc + seg); \
        } else {                                                                       \
            int tap = kc >> 10, ca = (kc & 1023) + seg;                                \
            int rg0 = m0 + rowA, rg1 = m0 + 64 + rowA;                                 \
            ra0 = make_float4(0.f, 0.f, 0.f, 0.f);                                     \
            ra1 = make_float4(0.f, 0.f, 0.f, 0.f);                                     \
            if (((rg0 & (SEQ - 1)) + tap) >= 2)                                        \
                ra0 = *(const float4*)(A + (size_t)(rg0 + tap - 2) * aStride + ca);    \
            if (((rg1 & (SEQ - 1)) + tap) >= 2)                                        \
                ra1 = *(const float4*)(A + (size_t)(rg1 + tap - 2) * aStride + ca);    \
        } } while (0)
    #define CPB(c, s) do {                                                             \
        const float* src = Bb + (size_t)((c) * KC + bK) * (2 * N) + 2 * n0 + bC16;     \
        uint32_t dst = bs + ((((s) * KC + bK) * 256 + bC16) << 2);                     \
        cpasync16(dst, src);                                                           \
        cpasync16(dst + 16, src + 4);                                                  \
        cpasync16(dst + 32, src + 8);                                                  \
        cpasync16(dst + 48, src + 12);                                                 \
        CP_COMMIT(); } while (0)
    #define STSA(s) do {                                                               \
        float* ab = AsP + ((s) * KC + seg) * 128 + rowA;                               \
        ab[0] = ra0.x; ab[128] = ra0.y; ab[256] = ra0.z; ab[384] = ra0.w;              \
        ab += 64;                                                                      \
        ab[0] = ra1.x; ab[128] = ra1.y; ab[256] = ra1.z; ab[384] = ra1.w;              \
    } while (0)

    LOADA(0); CPB(0, 0);
    STSA(0); CP_WAIT0(); __syncthreads();

    for (int c = 0; c < L; c++) {
        int s = c & 1;
        if (c + 1 < L) { LOADA(c + 1); CPB(c + 1, s ^ 1); }
        #pragma unroll
        for (int k = 0; k < KC; k++) {
            const float* Ak = AsP + (s * KC + k) * 128;
            const float* Bk = BsP + (s * KC + k) * 256;
            unsigned long long au[4], bd[8];
            *(float4*)&au[0] = *(const float4*)&Ak[ty * 4];
            *(float4*)&au[2] = *(const float4*)&Ak[64 + ty * 4];
            *(float4*)&bd[0] = *(const float4*)&Bk[tx * 8];          // (b0,b0,b1,b1)
            *(float4*)&bd[2] = *(const float4*)&Bk[tx * 8 + 4];      // (b2,b2,b3,b3)
            *(float4*)&bd[4] = *(const float4*)&Bk[128 + tx * 8];
            *(float4*)&bd[6] = *(const float4*)&Bk[128 + tx * 8 + 4];
            #pragma unroll
            for (int i = 0; i < 4; i++)
                #pragma unroll
                for (int j = 0; j < 8; j++) fma2(acc2[i][j], au[i], bd[j]);
        }
        if (c + 1 < L) { STSA(s ^ 1); CP_WAIT0(); __syncthreads(); }
    }

    #pragma unroll
    for (int i = 0; i < 8; i++) {
        int r = (i < 4) ? (ty * 4 + i) : (64 + ty * 4 + i - 4);
        int tok = stok[r];
        float* yr = Y + (size_t)tok * N + n0;
        float v[8];
        #pragma unroll
        for (int j = 0; j < 8; j++) {
            float lo, hi;
            upk2(acc2[i >> 1][j], lo, hi);
            v[j] = (i & 1) ? hi : lo;
        }
        *(float4*)(yr + tx * 4)      = make_float4(v[0], v[1], v[2], v[3]);
        *(float4*)(yr + 64 + tx * 4) = make_float4(v[4], v[5], v[6], v[7]);
    }
}

// ---------------- triple norm ----------------
__global__ __launch_bounds__(256) void k_triple_norm(const float* __restrict__ Y,
                                                     float* __restrict__ Z) {
    __shared__ float sm[8];
    int t = blockIdx.x, tid = threadIdx.x;
    const float* row = Y + (size_t)t * TI3;
    float v[4];
    float ls = 0.f;
    #pragma unroll
    for (int i = 0; i < 4; i++) {
        int c = tid + 256 * i;
        float r = fmaxf(row[c], 0.f);
        v[i] = r * r * r * row[IDIM + c] + row[2 * IDIM + c];
        ls += v[i];
    }
    #pragma unroll
    for (int o = 16; o >= 1; o >>= 1) ls += __shfl_xor_sync(0xffffffffu, ls, o);
    if ((tid & 31) == 0) sm[tid >> 5] = ls;
    __syncthreads();
    float mean = (sm[0] + sm[1] + sm[2] + sm[3] + sm[4] + sm[5] + sm[6] + sm[7]) * (1.0f / 1024.0f);
    __syncthreads();
    float ss = 0.f;
    #pragma unroll
    for (int i = 0; i < 4; i++) { float d = v[i] - mean; ss += d * d; }
    #pragma unroll
    for (int o = 16; o >= 1; o >>= 1) ss += __shfl_xor_sync(0xffffffffu, ss, o);
    if ((tid & 31) == 0) sm[tid >> 5] = ss;
    __syncthreads();
    float tot = sm[0] + sm[1] + sm[2] + sm[3] + sm[4] + sm[5] + sm[6] + sm[7];
    float rstd = sqrtf(1024.0f / tot);
    #pragma unroll
    for (int i = 0; i < 4; i++)
        Z[(size_t)t * IDIM + tid + 256 * i] = (v[i] - mean) * rstd;
}

// ---------------- host ----------------
extern "C" void kernel_launch(void* const* d_in, const int* in_sizes, int n_in,
                              void* d_out, int out_size) {
    const float* inp   = (const float*)d_in[0];
    const float* w0    = (const float*)d_in[1];
    const float* gate0 = (const float*)d_in[2];
    const float* w1    = (const float*)d_in[3];
    const float* w2    = (const float*)d_in[4];
    const float* gate2 = (const float*)d_in[5];
    float* out = (float*)d_out;

    void* p;  cudaGetSymbolAddress(&p, g_scratch);
    void* pi; cudaGetSymbolAddress(&pi, g_iscr);
    float* fs = (float*)p;
    int*   is = (int*)pi;

    float* xin   = fs + OFF_XIN;
    float* big   = fs + OFF_BIG;
    float* tn1   = fs + OFF_TN1;
    float* tn2   = fs + OFF_TN2;
    float* y2    = fs + OFF_Y2;
    float* gates = fs + OFF_GATES;
    float* scl   = fs + OFF_SCALE;
    float* Ag    = fs + OFF_AG;
    float* w0d   = fs + OFF_W0D;
    float* w1td  = fs + OFF_W1TD;
    float* w2d   = fs + OFF_W2D;
    int* ord  = is;
    int* perm = is + 131072;

    cudaFuncSetAttribute(k_sort, cudaFuncAttributeMaxDynamicSharedMemorySize, 65536);
    cudaFuncSetAttribute(k_gemm_f32, cudaFuncAttributeMaxDynamicSharedMemorySize, GEMM_SMEM);

    // ---- weight prep (dup layouts) ----
    k_dup<<<98304, 256>>>(w0, w0d);                       // 16x512x3072 -> dup
    k_w1t<<<dim3(96, 32, 3), dim3(32, 8)>>>(w1, w1td);    // transposed + dup
    k_dup<<<32768, 256>>>(w2, w2d);                       // 16x1024x512 -> dup

    // ---- MoE 1 ----
    k_transpose_in<<<dim3(64, 16, 4), dim3(32, 8)>>>(inp, xin);
    k_logits<<<512, 256>>>(xin, gate0, gates, FDIM);
    k_sort<<<16, 1024, 65536>>>(gates, ord);
    k_greedy<<<1, 1024>>>(ord, perm);
    k_scale<<<32, 256>>>(perm, gates, scl);
    k_fgather<<<dim3(2, 8192), 256>>>(xin, perm, scl, Ag, FDIM);
    k_gemm_f32<<<dim3(24, 4, 16), 256, GEMM_SMEM>>>(Ag, w0d, perm, big, TI3, FDIM, FDIM, 0);
    k_triple_norm<<<8192, 256>>>(big, tn1);

    // ---- causal conv ----
    k_gemm_f32<<<dim3(24, 64, 1), 256, GEMM_SMEM>>>(tn1, w1td, nullptr, big, TI3, TI3, IDIM, 1);
    k_triple_norm<<<8192, 256>>>(big, tn2);

    // ---- MoE 2 ----
    k_logits<<<512, 256>>>(tn2, gate2, gates, IDIM);
    k_sort<<<16, 1024, 65536>>>(gates, ord);
    k_greedy<<<1, 1024>>>(ord, perm);
    k_scale<<<32, 256>>>(perm, gates, scl);
    k_fgather<<<dim3(4, 8192), 256>>>(tn2, perm, scl, Ag, IDIM);
    k_gemm_f32<<<dim3(4, 4, 16), 256, GEMM_SMEM>>>(Ag, w2d, perm, y2, FDIM, IDIM, IDIM, 0);

    k_transpose_out<<<dim3(64, 16, 4), dim3(32, 8)>>>(y2, out);
}

// round 15
// speedup vs baseline: 1.9291x; 1.9291x over previous
#include <cuda_runtime.h>
#include <cstdint>

#define NTOK   8192
#define NEXP   16
#define CAP    512
#define FDIM   512
#define IDIM   1024
#define TI3    3072
#define SEQ    2048

#define OFF_XIN   0u
#define OFF_BIG   4194304u
#define OFF_TN1   29360128u
#define OFF_TN2   37748736u
#define OFF_Y2    46137344u
#define OFF_GATES 50331648u
#define OFF_SCALE 50462720u
#define OFF_W1T   50470912u
#define OFF_AG    59908096u
#define SCRATCH_FLOATS 68296704u

__device__ float g_scratch[SCRATCH_FLOATS];
__device__ int   g_iscr[131072 + 8192];   // ord | perm

__device__ __forceinline__ uint32_t s2u(const void* p) {
    uint32_t r;
    asm("{ .reg .u64 t; cvta.to.shared.u64 t, %1; cvt.u32.u64 %0, t; }" : "=r"(r) : "l"(p));
    return r;
}
__device__ __forceinline__ void cpasync16(uint32_t dst, const void* src) {
    asm volatile("cp.async.cg.shared.global [%0], [%1], 16;" :: "r"(dst), "l"(src));
}
#define CP_COMMIT() asm volatile("cp.async.commit_group;" ::: "memory")
#define CP_WAIT0()  asm volatile("cp.async.wait_group 0;" ::: "memory")

// packed fp32 helpers
__device__ __forceinline__ unsigned long long pk2(float lo, float hi) {
    unsigned long long r;
    asm("mov.b64 %0, {%1, %2};" : "=l"(r) : "f"(lo), "f"(hi));
    return r;
}
__device__ __forceinline__ void upk2(unsigned long long v, float& lo, float& hi) {
    asm("mov.b64 {%0, %1}, %2;" : "=f"(lo), "=f"(hi) : "l"(v));
}
__device__ __forceinline__ void fma2(unsigned long long& d, unsigned long long a,
                                     unsigned long long b) {
    asm("fma.rn.f32x2 %0, %1, %2, %0;" : "+l"(d) : "l"(a), "l"(b));
}

// ---------------- transposes ----------------
__global__ void k_transpose_in(const float* __restrict__ in, float* __restrict__ out) {
    __shared__ float tile[32][33];
    int b = blockIdx.z, s0 = blockIdx.x * 32, f0 = blockIdx.y * 32;
    int tx = threadIdx.x, ty = threadIdx.y;
    #pragma unroll
    for (int r = ty; r < 32; r += 8)
        tile[r][tx] = in[((size_t)(b * FDIM + f0 + r)) * SEQ + s0 + tx];
    __syncthreads();
    #pragma unroll
    for (int r = ty; r < 32; r += 8)
        out[((size_t)(b * SEQ + s0 + r)) * FDIM + f0 + tx] = tile[tx][r];
}

__global__ void k_transpose_out(const float* __restrict__ y2, float* __restrict__ out) {
    __shared__ float tile[32][33];
    int b = blockIdx.z, s0 = blockIdx.x * 32, f0 = blockIdx.y * 32;
    int tx = threadIdx.x, ty = threadIdx.y;
    #pragma unroll
    for (int r = ty; r < 32; r += 8)
        tile[r][tx] = y2[((size_t)(b * SEQ + s0 + r)) * FDIM + f0 + tx];
    __syncthreads();
    #pragma unroll
    for (int r = ty; r < 32; r += 8)
        out[((size_t)(b * FDIM + f0 + r)) * SEQ + s0 + tx] = tile[tx][r];
}

// w1 [O][I][k] -> w1t [k*1024+i][o]
__global__ void k_w1t(const float* __restrict__ w1, float* __restrict__ w1t) {
    __shared__ float tile[32][33];
    int k = blockIdx.z, o0 = blockIdx.x * 32, i0 = blockIdx.y * 32;
    int tx = threadIdx.x, ty = threadIdx.y;
    #pragma unroll
    for (int r = ty; r < 32; r += 8)
        tile[r][tx] = w1[((size_t)(o0 + r) * IDIM + i0 + tx) * 3 + k];
    __syncthreads();
    #pragma unroll
    for (int r = ty; r < 32; r += 8)
        w1t[((size_t)k * IDIM + i0 + r) * TI3 + o0 + tx] = tile[tx][r];
}

// ---------------- gate logits + softmax ----------------
__global__ __launch_bounds__(256) void k_logits(const float* __restrict__ X,
                                                const float* __restrict__ G,
                                                float* __restrict__ gates, int K) {
    __shared__ float Xs[16][65];
    __shared__ float Gs[64][16];
    int t0 = blockIdx.x * 16, tid = threadIdx.x;
    int e = tid & 15, tl = tid >> 4;
    float acc = 0.f;
    for (int k0 = 0; k0 < K; k0 += 64) {
        __syncthreads();
        #pragma unroll
        for (int r = 0; r < 4; r++) {
            int j = tid + 256 * r;
            Xs[j >> 6][j & 63] = X[(size_t)(t0 + (j >> 6)) * K + k0 + (j & 63)];
        }
        #pragma unroll
        for (int r = 0; r < 4; r++) {
            int j = tid + 256 * r;
            Gs[j >> 4][j & 15] = G[(size_t)(k0 + (j >> 4)) * NEXP + (j & 15)];
        }
        __syncthreads();
        #pragma unroll
        for (int k = 0; k < 64; k++) acc += Xs[tl][k] * Gs[k][e];
    }
    float m = acc;
    #pragma unroll
    for (int o = 8; o >= 1; o >>= 1) m = fmaxf(m, __shfl_xor_sync(0xffffffffu, m, o, 16));
    float ex = expf(acc - m);
    float s = ex;
    #pragma unroll
    for (int o = 8; o >= 1; o >>= 1) s += __shfl_xor_sync(0xffffffffu, s, o, 16);
    gates[(size_t)(t0 + tl) * NEXP + e] = ex / s;
}

// ---------------- per-expert descending sort ----------------
__global__ __launch_bounds__(1024) void k_sort(const float* __restrict__ gates,
                                               int* __restrict__ ord) {
    extern __shared__ unsigned long long smsort[];
    int e = blockIdx.x, tid = threadIdx.x;
    #pragma unroll
    for (int r = 0; r < 8; r++) {
        int i = r * 1024 + tid;
        unsigned fb = __float_as_uint(gates[(size_t)i * NEXP + e]);
        smsort[i] = ((unsigned long long)fb << 32) | (unsigned)(NTOK - 1 - i);
    }
    __syncthreads();
    for (int k = 2; k <= NTOK; k <<= 1) {
        for (int j = k >> 1; j > 0; j >>= 1) {
            #pragma unroll
            for (int r = 0; r < 8; r++) {
                int i = r * 1024 + tid;
                int l = i ^ j;
                if (l > i) {
                    unsigned long long a = smsort[i], b = smsort[l];
                    bool desc = ((i & k) == 0);
                    if ((a < b) == desc) { smsort[i] = b; smsort[l] = a; }
                }
            }
            __syncthreads();
        }
    }
    #pragma unroll
    for (int r = 0; r < 8; r++) {
        int i = r * 1024 + tid;
        ord[e * NTOK + i] = NTOK - 1 - (int)(unsigned)(smsort[i] & 0xffffffffu);
    }
}

// ---------------- greedy capacity assignment + fused gate-scale ----------------
__global__ __launch_bounds__(1024) void k_greedy(const int* __restrict__ ord,
                                                 int* __restrict__ perm,
                                                 const float* __restrict__ gates,
                                                 float* __restrict__ scl) {
    __shared__ unsigned assigned[NTOK / 32];
    __shared__ int wsums[32];
    int tid = threadIdx.x, lane = tid & 31, wid = tid >> 5;
    if (tid < NTOK / 32) assigned[tid] = 0u;
    __syncthreads();
    for (int e = 0; e < NEXP; e++) {
        int toks[8];
        int flags = 0, cnt = 0;
        #pragma unroll
        for (int i = 0; i < 8; i++) {
            int tok = ord[e * NTOK + tid * 8 + i];
            toks[i] = tok;
            bool freetok = !((assigned[tok >> 5] >> (tok & 31)) & 1u);
            flags |= ((int)freetok) << i;
            cnt += (int)freetok;
        }
        int v = cnt;
        #pragma unroll
        for (int o = 1; o < 32; o <<= 1) {
            int n = __shfl_up_sync(0xffffffffu, v, o);
            if (lane >= o) v += n;
        }
        if (lane == 31) wsums[wid] = v;
        __syncthreads();
        if (wid == 0) {
            int w = wsums[lane];
            #pragma unroll
            for (int o = 1; o < 32; o <<= 1) {
                int n = __shfl_up_sync(0xffffffffu, w, o);
                if (lane >= o) w += n;
            }
            wsums[lane] = w;
        }
        __syncthreads();
        int r = v - cnt + (wid ? wsums[wid - 1] : 0);
        #pragma unroll
        for (int i = 0; i < 8; i++) {
            if ((flags >> i) & 1) {
                if (r < CAP) {
                    int tok = toks[i];
                    perm[r * NEXP + e] = tok;
                    atomicOr(&assigned[tok >> 5], 1u << (tok & 31));
                }
                r++;
            }
        }
        __syncthreads();
    }
    // fused scale: global writes above are visible block-wide after the syncthreads
    #pragma unroll
    for (int r = 0; r < 8; r++) {
        int p = r * 1024 + tid;
        int tok = perm[p];
        scl[tok] = gates[(size_t)tok * NEXP + (p >> 9)];
    }
}

__global__ void k_fgather(const float* __restrict__ X, const int* __restrict__ perm,
                          const float* __restrict__ scl, float* __restrict__ Ag, int K) {
    int col = blockIdx.x * 256 + threadIdx.x;
    int q = blockIdx.y;
    int tok = perm[(q & 511) * NEXP + (q >> 9)];
    Ag[(size_t)q * K + col] = X[(size_t)tok * K + col] * scl[tok];
}

// ================= fp32 GEMM, f32x2 inner loop with alias-packed A (R13) =================
#define KC 16
__global__ __launch_bounds__(256, 2) void k_gemm_f32(
    const float* __restrict__ A, const float* __restrict__ B,
    const int* __restrict__ perm, float* __restrict__ Y,
    int N, int K, int aStride, int isConv)
{
    __shared__ float As[2][KC][128];
    __shared__ float Bs[2][KC][128];
    __shared__ int stok[128];

    int tid = threadIdx.x;
    int e = blockIdx.z, n0 = blockIdx.x * 128, by = blockIdx.y;
    int m0 = isConv ? by * 128 : e * CAP + by * 128;
    if (tid < 128) stok[tid] = perm ? perm[(by * 128 + tid) * NEXP + e] : (m0 + tid);

    const float* Bb = B + (size_t)e * K * N;
    int tx = tid & 15, ty = tid >> 4;
    int rowA = tid >> 2, seg = (tid & 3) * 4;
    int bK = tid >> 4, bC = (tid & 15) * 8;
    uint32_t bs = s2u(&Bs[0][0][0]);

    unsigned long long acc2[4][8];
    #pragma unroll
    for (int i = 0; i < 4; i++)
        #pragma unroll
        for (int j = 0; j < 8; j++) acc2[i][j] = 0ull;

    float4 ra0, ra1;
    int L = K / KC;

    #define LOADA(c) do {                                                              \
        int kc = (c) * KC;                                                             \
        if (!isConv) {                                                                 \
            ra0 = *(const float4*)(A + (size_t)(m0 + rowA) * aStride + kc + seg);      \
            ra1 = *(const float4*)(A + (size_t)(m0 + 64 + rowA) * aStride + kc + seg); \
        } else {                                                                       \
            int tap = kc >> 10, ca = (kc & 1023) + seg;                                \
            int rg0 = m0 + rowA, rg1 = m0 + 64 + rowA;                                 \
            ra0 = make_float4(0.f, 0.f, 0.f, 0.f);                                     \
            ra1 = make_float4(0.f, 0.f, 0.f, 0.f);                                     \
            if (((rg0 & (SEQ - 1)) + tap) >= 2)                                        \
                ra0 = *(const float4*)(A + (size_t)(rg0 + tap - 2) * aStride + ca);    \
            if (((rg1 & (SEQ - 1)) + tap) >= 2)                                        \
                ra1 = *(const float4*)(A + (size_t)(rg1 + tap - 2) * aStride + ca);    \
        } } while (0)
    #define CPB(c, s) do {                                                             \
        const float* src = Bb + (size_t)((c) * KC + bK) * N + n0 + bC;                 \
        uint32_t dst = bs + ((((s) * KC + bK) * 128 + bC) << 2);                       \
        cpasync16(dst, src);                                                           \
        cpasync16(dst + 16, src + 4);                                                  \
        CP_COMMIT(); } while (0)
    #define STSA(s) do {                                                               \
        As[s][seg + 0][rowA] = ra0.x; As[s][seg + 1][rowA] = ra0.y;                    \
        As[s][seg + 2][rowA] = ra0.z; As[s][seg + 3][rowA] = ra0.w;                    \
        As[s][seg + 0][64 + rowA] = ra1.x; As[s][seg + 1][64 + rowA] = ra1.y;          \
        As[s][seg + 2][64 + rowA] = ra1.z; As[s][seg + 3][64 + rowA] = ra1.w;          \
    } while (0)

    LOADA(0); CPB(0, 0);
    STSA(0); CP_WAIT0(); __syncthreads();

    for (int c = 0; c < L; c++) {
        int s = c & 1;
        if (c + 1 < L) { LOADA(c + 1); CPB(c + 1, s ^ 1); }
        #pragma unroll
        for (int k = 0; k < KC; k++) {
            unsigned long long au[4];
            float bq[8];
            *(float4*)&au[0] = *(const float4*)&As[s][k][ty * 4];
            *(float4*)&au[2] = *(const float4*)&As[s][k][64 + ty * 4];
            *(float4*)&bq[0] = *(const float4*)&Bs[s][k][tx * 4];
            *(float4*)&bq[4] = *(const float4*)&Bs[s][k][64 + tx * 4];
            unsigned long long bd[8];
            #pragma unroll
            for (int j = 0; j < 8; j++) bd[j] = pk2(bq[j], bq[j]);
            #pragma unroll
            for (int i = 0; i < 4; i++)
                #pragma unroll
                for (int j = 0; j < 8; j++) fma2(acc2[i][j], au[i], bd[j]);
        }
        if (c + 1 < L) { STSA(s ^ 1); CP_WAIT0(); __syncthreads(); }
    }

    #pragma unroll
    for (int i = 0; i < 8; i++) {
        int r = (i < 4) ? (ty * 4 + i) : (64 + ty * 4 + i - 4);
        int tok = stok[r];
        float* yr = Y + (size_t)tok * N + n0;
        float v[8];
        #pragma unroll
        for (int j = 0; j < 8; j++) {
            float lo, hi;
            upk2(acc2[i >> 1][j], lo, hi);
            v[j] = (i & 1) ? hi : lo;
        }
        *(float4*)(yr + tx * 4)      = make_float4(v[0], v[1], v[2], v[3]);
        *(float4*)(yr + 64 + tx * 4) = make_float4(v[4], v[5], v[6], v[7]);
    }
}

// ---------------- triple norm ----------------
__global__ __launch_bounds__(256) void k_triple_norm(const float* __restrict__ Y,
                                                     float* __restrict__ Z) {
    __shared__ float sm[8];
    int t = blockIdx.x, tid = threadIdx.x;
    const float* row = Y + (size_t)t * TI3;
    float v[4];
    float ls = 0.f;
    #pragma unroll
    for (int i = 0; i < 4; i++) {
        int c = tid + 256 * i;
        float r = fmaxf(row[c], 0.f);
        v[i] = r * r * r * row[IDIM + c] + row[2 * IDIM + c];
        ls += v[i];
    }
    #pragma unroll
    for (int o = 16; o >= 1; o >>= 1) ls += __shfl_xor_sync(0xffffffffu, ls, o);
    if ((tid & 31) == 0) sm[tid >> 5] = ls;
    __syncthreads();
    float mean = (sm[0] + sm[1] + sm[2] + sm[3] + sm[4] + sm[5] + sm[6] + sm[7]) * (1.0f / 1024.0f);
    __syncthreads();
    float ss = 0.f;
    #pragma unroll
    for (int i = 0; i < 4; i++) { float d = v[i] - mean; ss += d * d; }
    #pragma unroll
    for (int o = 16; o >= 1; o >>= 1) ss += __shfl_xor_sync(0xffffffffu, ss, o);
    if ((tid & 31) == 0) sm[tid >> 5] = ss;
    __syncthreads();
    float tot = sm[0] + sm[1] + sm[2] + sm[3] + sm[4] + sm[5] + sm[6] + sm[7];
    float rstd = sqrtf(1024.0f / tot);
    #pragma unroll
    for (int i = 0; i < 4; i++)
        Z[(size_t)t * IDIM + tid + 256 * i] = (v[i] - mean) * rstd;
}

// ---------------- host ----------------
extern "C" void kernel_launch(void* const* d_in, const int* in_sizes, int n_in,
                              void* d_out, int out_size) {
    const float* inp   = (const float*)d_in[0];
    const float* w0    = (const float*)d_in[1];
    const float* gate0 = (const float*)d_in[2];
    const float* w1    = (const float*)d_in[3];
    const float* w2    = (const float*)d_in[4];
    const float* gate2 = (const float*)d_in[5];
    float* out = (float*)d_out;

    void* p;  cudaGetSymbolAddress(&p, g_scratch);
    void* pi; cudaGetSymbolAddress(&pi, g_iscr);
    float* fs = (float*)p;
    int*   is = (int*)pi;

    float* xin   = fs + OFF_XIN;
    float* big   = fs + OFF_BIG;
    float* tn1   = fs + OFF_TN1;
    float* tn2   = fs + OFF_TN2;
    float* y2    = fs + OFF_Y2;
    float* gates = fs + OFF_GATES;
    float* scl   = fs + OFF_SCALE;
    float* w1t   = fs + OFF_W1T;
    float* Ag    = fs + OFF_AG;
    int* ord  = is;
    int* perm = is + 131072;

    cudaFuncSetAttribute(k_sort, cudaFuncAttributeMaxDynamicSharedMemorySize, 65536);

    // ---- MoE 1 ----
    k_transpose_in<<<dim3(64, 16, 4), dim3(32, 8)>>>(inp, xin);
    k_logits<<<512, 256>>>(xin, gate0, gates, FDIM);
    k_sort<<<16, 1024, 65536>>>(gates, ord);
    k_greedy<<<1, 1024>>>(ord, perm, gates, scl);
    k_fgather<<<dim3(2, 8192), 256>>>(xin, perm, scl, Ag, FDIM);
    k_gemm_f32<<<dim3(24, 4, 16), 256>>>(Ag, w0, perm, big, TI3, FDIM, FDIM, 0);
    k_triple_norm<<<8192, 256>>>(big, tn1);

    // ---- causal conv ----
    k_w1t<<<dim3(96, 32, 3), dim3(32, 8)>>>(w1, w1t);
    k_gemm_f32<<<dim3(24, 64, 1), 256>>>(tn1, w1t, nullptr, big, TI3, TI3, IDIM, 1);
    k_triple_norm<<<8192, 256>>>(big, tn2);

    // ---- MoE 2 ----
    k_logits<<<512, 256>>>(tn2, gate2, gates, IDIM);
    k_sort<<<16, 1024, 65536>>>(gates, ord);
    k_greedy<<<1, 1024>>>(ord, perm, gates, scl);
    k_fgather<<<dim3(4, 8192), 256>>>(tn2, perm, scl, Ag, IDIM);
    k_gemm_f32<<<dim3(4, 4, 16), 256>>>(Ag, w2, perm, y2, FDIM, IDIM, IDIM, 0);

    k_transpose_out<<<dim3(64, 16, 4), dim3(32, 8)>>>(y2, out);
}

// round 16
// speedup vs baseline: 1.9597x; 1.0158x over previous
#include <cuda_runtime.h>
#include <cstdint>

#define NTOK   8192
#define NEXP   16
#define CAP    512
#define FDIM   512
#define IDIM   1024
#define TI3    3072
#define SEQ    2048

#define OFF_XIN   0u
#define OFF_BIG   4194304u
#define OFF_TN1   29360128u
#define OFF_TN2   37748736u
#define OFF_Y2    46137344u
#define OFF_GATES 50331648u
#define OFF_SCALE 50462720u
#define OFF_W1T   50470912u
#define SCRATCH_FLOATS 59908096u

__device__ float g_scratch[SCRATCH_FLOATS];
__device__ int   g_iscr[131072 + 8192];   // ord | perm

__device__ __forceinline__ uint32_t s2u(const void* p) {
    uint32_t r;
    asm("{ .reg .u64 t; cvta.to.shared.u64 t, %1; cvt.u32.u64 %0, t; }" : "=r"(r) : "l"(p));
    return r;
}
__device__ __forceinline__ void cpasync16(uint32_t dst, const void* src) {
    asm volatile("cp.async.cg.shared.global [%0], [%1], 16;" :: "r"(dst), "l"(src));
}
#define CP_COMMIT() asm volatile("cp.async.commit_group;" ::: "memory")
#define CP_WAIT0()  asm volatile("cp.async.wait_group 0;" ::: "memory")

// packed fp32 helpers
__device__ __forceinline__ unsigned long long pk2(float lo, float hi) {
    unsigned long long r;
    asm("mov.b64 %0, {%1, %2};" : "=l"(r) : "f"(lo), "f"(hi));
    return r;
}
__device__ __forceinline__ void upk2(unsigned long long v, float& lo, float& hi) {
    asm("mov.b64 {%0, %1}, %2;" : "=f"(lo), "=f"(hi) : "l"(v));
}
__device__ __forceinline__ void fma2(unsigned long long& d, unsigned long long a,
                                     unsigned long long b) {
    asm("fma.rn.f32x2 %0, %1, %2, %0;" : "+l"(d) : "l"(a), "l"(b));
}

// ---------------- transposes ----------------
__global__ void k_transpose_in(const float* __restrict__ in, float* __restrict__ out) {
    __shared__ float tile[32][33];
    int b = blockIdx.z, s0 = blockIdx.x * 32, f0 = blockIdx.y * 32;
    int tx = threadIdx.x, ty = threadIdx.y;
    #pragma unroll
    for (int r = ty; r < 32; r += 8)
        tile[r][tx] = in[((size_t)(b * FDIM + f0 + r)) * SEQ + s0 + tx];
    __syncthreads();
    #pragma unroll
    for (int r = ty; r < 32; r += 8)
        out[((size_t)(b * SEQ + s0 + r)) * FDIM + f0 + tx] = tile[tx][r];
}

__global__ void k_transpose_out(const float* __restrict__ y2, float* __restrict__ out) {
    __shared__ float tile[32][33];
    int b = blockIdx.z, s0 = blockIdx.x * 32, f0 = blockIdx.y * 32;
    int tx = threadIdx.x, ty = threadIdx.y;
    #pragma unroll
    for (int r = ty; r < 32; r += 8)
        tile[r][tx] = y2[((size_t)(b * SEQ + s0 + r)) * FDIM + f0 + tx];
    __syncthreads();
    #pragma unroll
    for (int r = ty; r < 32; r += 8)
        out[((size_t)(b * FDIM + f0 + r)) * SEQ + s0 + tx] = tile[tx][r];
}

// w1 [O][I][k] -> w1t [k*1024+i][o], single pass over w1
__global__ void k_w1t(const float* __restrict__ w1, float* __restrict__ w1t) {
    __shared__ float tile[3][32][33];
    int o0 = blockIdx.x * 32, i0 = blockIdx.y * 32;
    int tx = threadIdx.x, ty = threadIdx.y;
    #pragma unroll
    for (int r = ty; r < 32; r += 8) {
        const float* src = w1 + ((size_t)(o0 + r) * IDIM + i0 + tx) * 3;
        tile[0][r][tx] = src[0];
        tile[1][r][tx] = src[1];
        tile[2][r][tx] = src[2];
    }
    __syncthreads();
    #pragma unroll
    for (int k = 0; k < 3; k++)
        #pragma unroll
        for (int r = ty; r < 32; r += 8)
            w1t[((size_t)k * IDIM + i0 + r) * TI3 + o0 + tx] = tile[k][tx][r];
}

// ---------------- gate logits + softmax ----------------
__global__ __launch_bounds__(256) void k_logits(const float* __restrict__ X,
                                                const float* __restrict__ G,
                                                float* __restrict__ gates, int K) {
    __shared__ float Xs[16][65];
    __shared__ float Gs[64][16];
    int t0 = blockIdx.x * 16, tid = threadIdx.x;
    int e = tid & 15, tl = tid >> 4;
    float acc = 0.f;
    for (int k0 = 0; k0 < K; k0 += 64) {
        __syncthreads();
        #pragma unroll
        for (int r = 0; r < 4; r++) {
            int j = tid + 256 * r;
            Xs[j >> 6][j & 63] = X[(size_t)(t0 + (j >> 6)) * K + k0 + (j & 63)];
        }
        #pragma unroll
        for (int r = 0; r < 4; r++) {
            int j = tid + 256 * r;
            Gs[j >> 4][j & 15] = G[(size_t)(k0 + (j >> 4)) * NEXP + (j & 15)];
        }
        __syncthreads();
        #pragma unroll
        for (int k = 0; k < 64; k++) acc += Xs[tl][k] * Gs[k][e];
    }
    float m = acc;
    #pragma unroll
    for (int o = 8; o >= 1; o >>= 1) m = fmaxf(m, __shfl_xor_sync(0xffffffffu, m, o, 16));
    float ex = expf(acc - m);
    float s = ex;
    #pragma unroll
    for (int o = 8; o >= 1; o >>= 1) s += __shfl_xor_sync(0xffffffffu, s, o, 16);
    gates[(size_t)(t0 + tl) * NEXP + e] = ex / s;
}

// ---------------- per-expert descending sort ----------------
__global__ __launch_bounds__(1024) void k_sort(const float* __restrict__ gates,
                                               int* __restrict__ ord) {
    extern __shared__ unsigned long long smsort[];
    int e = blockIdx.x, tid = threadIdx.x;
    #pragma unroll
    for (int r = 0; r < 8; r++) {
        int i = r * 1024 + tid;
        unsigned fb = __float_as_uint(gates[(size_t)i * NEXP + e]);
        smsort[i] = ((unsigned long long)fb << 32) | (unsigned)(NTOK - 1 - i);
    }
    __syncthreads();
    for (int k = 2; k <= NTOK; k <<= 1) {
        for (int j = k >> 1; j > 0; j >>= 1) {
            #pragma unroll
            for (int r = 0; r < 8; r++) {
                int i = r * 1024 + tid;
                int l = i ^ j;
                if (l > i) {
                    unsigned long long a = smsort[i], b = smsort[l];
                    bool desc = ((i & k) == 0);
                    if ((a < b) == desc) { smsort[i] = b; smsort[l] = a; }
                }
            }
            __syncthreads();
        }
    }
    #pragma unroll
    for (int r = 0; r < 8; r++) {
        int i = r * 1024 + tid;
        ord[e * NTOK + i] = NTOK - 1 - (int)(unsigned)(smsort[i] & 0xffffffffu);
    }
}

// ---------------- greedy capacity assignment + fused gate-scale ----------------
__global__ __launch_bounds__(1024) void k_greedy(const int* __restrict__ ord,
                                                 int* __restrict__ perm,
                                                 const float* __restrict__ gates,
                                                 float* __restrict__ scl) {
    __shared__ unsigned assigned[NTOK / 32];
    __shared__ int wsums[32];
    int tid = threadIdx.x, lane = tid & 31, wid = tid >> 5;
    if (tid < NTOK / 32) assigned[tid] = 0u;
    __syncthreads();
    for (int e = 0; e < NEXP; e++) {
        int toks[8];
        int flags = 0, cnt = 0;
        #pragma unroll
        for (int i = 0; i < 8; i++) {
            int tok = ord[e * NTOK + tid * 8 + i];
            toks[i] = tok;
            bool freetok = !((assigned[tok >> 5] >> (tok & 31)) & 1u);
            flags |= ((int)freetok) << i;
            cnt += (int)freetok;
        }
        int v = cnt;
        #pragma unroll
        for (int o = 1; o < 32; o <<= 1) {
            int n = __shfl_up_sync(0xffffffffu, v, o);
            if (lane >= o) v += n;
        }
        if (lane == 31) wsums[wid] = v;
        __syncthreads();
        if (wid == 0) {
            int w = wsums[lane];
            #pragma unroll
            for (int o = 1; o < 32; o <<= 1) {
                int n = __shfl_up_sync(0xffffffffu, w, o);
                if (lane >= o) w += n;
            }
            wsums[lane] = w;
        }
        __syncthreads();
        int r = v - cnt + (wid ? wsums[wid - 1] : 0);
        #pragma unroll
        for (int i = 0; i < 8; i++) {
            if ((flags >> i) & 1) {
                if (r < CAP) {
                    int tok = toks[i];
                    perm[r * NEXP + e] = tok;
                    atomicOr(&assigned[tok >> 5], 1u << (tok & 31));
                }
                r++;
            }
        }
        __syncthreads();
    }
    #pragma unroll
    for (int r = 0; r < 8; r++) {
        int p = r * 1024 + tid;
        int tok = perm[p];
        scl[tok] = gates[(size_t)tok * NEXP + (p >> 9)];
    }
}

// ===== fp32 GEMM, f32x2; fused token-gather + gate-scale in the A path =====
#define KC 16
__global__ __launch_bounds__(256, 2) void k_gemm_f32(
    const float* __restrict__ A, const float* __restrict__ B,
    const int* __restrict__ perm, const float* __restrict__ scl,
    float* __restrict__ Y, int N, int K, int aStride, int isConv)
{
    __shared__ float As[2][KC][128];
    __shared__ float Bs[2][KC][128];
    __shared__ int   stok[128];
    __shared__ float ssc[128];

    int tid = threadIdx.x;
    int e = blockIdx.z, n0 = blockIdx.x * 128, by = blockIdx.y;
    int m0 = isConv ? by * 128 : e * CAP + by * 128;
    if (tid < 128) {
        int tok = perm ? perm[(by * 128 + tid) * NEXP + e] : (m0 + tid);
        stok[tid] = tok;
        ssc[tid]  = perm ? scl[tok] : 1.f;
    }
    __syncthreads();

    const float* Bb = B + (size_t)e * K * N;
    int tx = tid & 15, ty = tid >> 4;
    int rowA = tid >> 2, seg = (tid & 3) * 4;
    int bK = tid >> 4, bC = (tid & 15) * 8;
    uint32_t bs = s2u(&Bs[0][0][0]);

    int tokA0 = 0, tokA1 = 0;
    float sA0 = 1.f, sA1 = 1.f;
    if (!isConv) {
        tokA0 = stok[rowA];      sA0 = ssc[rowA];
        tokA1 = stok[64 + rowA]; sA1 = ssc[64 + rowA];
    }

    unsigned long long acc2[4][8];
    #pragma unroll
    for (int i = 0; i < 4; i++)
        #pragma unroll
        for (int j = 0; j < 8; j++) acc2[i][j] = 0ull;

    float4 ra0, ra1;
    int L = K / KC;

    #define LOADA(c) do {                                                              \
        int kc = (c) * KC;                                                             \
        if (!isConv) {                                                                 \
            ra0 = *(const float4*)(A + (size_t)tokA0 * aStride + kc + seg);            \
            ra1 = *(const float4*)(A + (size_t)tokA1 * aStride + kc + seg);            \
            ra0.x *= sA0; ra0.y *= sA0; ra0.z *= sA0; ra0.w *= sA0;                    \
            ra1.x *= sA1; ra1.y *= sA1; ra1.z *= sA1; ra1.w *= sA1;                    \
        } else {                                                                       \
            int tap = kc >> 10, ca = (kc & 1023) + seg;                                \
            int rg0 = m0 + rowA, rg1 = m0 + 64 + rowA;                                 \
            ra0 = make_float4(0.f, 0.f, 0.f, 0.f);                                     \
            ra1 = make_float4(0.f, 0.f, 0.f, 0.f);                                     \
            if (((rg0 & (SEQ - 1)) + tap) >= 2)                                        \
                ra0 = *(const float4*)(A + (size_t)(rg0 + tap - 2) * aStride + ca);    \
            if (((rg1 & (SEQ - 1)) + tap) >= 2)                                        \
                ra1 = *(const float4*)(A + (size_t)(rg1 + tap - 2) * aStride + ca);    \
        } } while (0)
    #define CPB(c, s) do {                                                             \
        const float* src = Bb + (size_t)((c) * KC + bK) * N + n0 + bC;                 \
        uint32_t dst = bs + ((((s) * KC + bK) * 128 + bC) << 2);                       \
        cpasync16(dst, src);                                                           \
        cpasync16(dst + 16, src + 4);                                                  \
        CP_COMMIT(); } while (0)
    #define STSA(s) do {                                                               \
        As[s][seg + 0][rowA] = ra0.x; As[s][seg + 1][rowA] = ra0.y;                    \
        As[s][seg + 2][rowA] = ra0.z; As[s][seg + 3][rowA] = ra0.w;                    \
        As[s][seg + 0][64 + rowA] = ra1.x; As[s][seg + 1][64 + rowA] = ra1.y;          \
        As[s][seg + 2][64 + rowA] = ra1.z; As[s][seg + 3][64 + rowA] = ra1.w;          \
    } while (0)

    LOADA(0); CPB(0, 0);
    STSA(0); CP_WAIT0(); __syncthreads();

    for (int c = 0; c < L; c++) {
        int s = c & 1;
        if (c + 1 < L) { LOADA(c + 1); CPB(c + 1, s ^ 1); }
        #pragma unroll
        for (int k = 0; k < KC; k++) {
            unsigned long long au[4];
            float bq[8];
            *(float4*)&au[0] = *(const float4*)&As[s][k][ty * 4];
            *(float4*)&au[2] = *(const float4*)&As[s][k][64 + ty * 4];
            *(float4*)&bq[0] = *(const float4*)&Bs[s][k][tx * 4];
            *(float4*)&bq[4] = *(const float4*)&Bs[s][k][64 + tx * 4];
            unsigned long long bd[8];
            #pragma unroll
            for (int j = 0; j < 8; j++) bd[j] = pk2(bq[j], bq[j]);
            #pragma unroll
            for (int i = 0; i < 4; i++)
                #pragma unroll
                for (int j = 0; j < 8; j++) fma2(acc2[i][j], au[i], bd[j]);
        }
        if (c + 1 < L) { STSA(s ^ 1); CP_WAIT0(); __syncthreads(); }
    }

    #pragma unroll
    for (int i = 0; i < 8; i++) {
        int r = (i < 4) ? (ty * 4 + i) : (64 + ty * 4 + i - 4);
        int tok = stok[r];
        float* yr = Y + (size_t)tok * N + n0;
        float v[8];
        #pragma unroll
        for (int j = 0; j < 8; j++) {
            float lo, hi;
            upk2(acc2[i >> 1][j], lo, hi);
            v[j] = (i & 1) ? hi : lo;
        }
        *(float4*)(yr + tx * 4)      = make_float4(v[0], v[1], v[2], v[3]);
        *(float4*)(yr + 64 + tx * 4) = make_float4(v[4], v[5], v[6], v[7]);
    }
}

// ---------------- triple norm ----------------
__global__ __launch_bounds__(256) void k_triple_norm(const float* __restrict__ Y,
                                                     float* __restrict__ Z) {
    __shared__ float sm[8];
    int t = blockIdx.x, tid = threadIdx.x;
    const float* row = Y + (size_t)t * TI3;
    float v[4];
    float ls = 0.f;
    #pragma unroll
    for (int i = 0; i < 4; i++) {
        int c = tid + 256 * i;
        float r = fmaxf(row[c], 0.f);
        v[i] = r * r * r * row[IDIM + c] + row[2 * IDIM + c];
        ls += v[i];
    }
    #pragma unroll
    for (int o = 16; o >= 1; o >>= 1) ls += __shfl_xor_sync(0xffffffffu, ls, o);
    if ((tid & 31) == 0) sm[tid >> 5] = ls;
    __syncthreads();
    float mean = (sm[0] + sm[1] + sm[2] + sm[3] + sm[4] + sm[5] + sm[6] + sm[7]) * (1.0f / 1024.0f);
    __syncthreads();
    float ss = 0.f;
    #pragma unroll
    for (int i = 0; i < 4; i++) { float d = v[i] - mean; ss += d * d; }
    #pragma unroll
    for (int o = 16; o >= 1; o >>= 1) ss += __shfl_xor_sync(0xffffffffu, ss, o);
    if ((tid & 31) == 0) sm[tid >> 5] = ss;
    __syncthreads();
    float tot = sm[0] + sm[1] + sm[2] + sm[3] + sm[4] + sm[5] + sm[6] + sm[7];
    float rstd = sqrtf(1024.0f / tot);
    #pragma unroll
    for (int i = 0; i < 4; i++)
        Z[(size_t)t * IDIM + tid + 256 * i] = (v[i] - mean) * rstd;
}

// ---------------- host ----------------
extern "C" void kernel_launch(void* const* d_in, const int* in_sizes, int n_in,
                              void* d_out, int out_size) {
    const float* inp   = (const float*)d_in[0];
    const float* w0    = (const float*)d_in[1];
    const float* gate0 = (const float*)d_in[2];
    const float* w1    = (const float*)d_in[3];
    const float* w2    = (const float*)d_in[4];
    const float* gate2 = (const float*)d_in[5];
    float* out = (float*)d_out;

    void* p;  cudaGetSymbolAddress(&p, g_scratch);
    void* pi; cudaGetSymbolAddress(&pi, g_iscr);
    float* fs = (float*)p;
    int*   is = (int*)pi;

    float* xin   = fs + OFF_XIN;
    float* big   = fs + OFF_BIG;
    float* tn1   = fs + OFF_TN1;
    float* tn2   = fs + OFF_TN2;
    float* y2    = fs + OFF_Y2;
    float* gates = fs + OFF_GATES;
    float* scl   = fs + OFF_SCALE;
    float* w1t   = fs + OFF_W1T;
    int* ord  = is;
    int* perm = is + 131072;

    cudaFuncSetAttribute(k_sort, cudaFuncAttributeMaxDynamicSharedMemorySize, 65536);

    // ---- MoE 1 ----
    k_transpose_in<<<dim3(64, 16, 4), dim3(32, 8)>>>(inp, xin);
    k_logits<<<512, 256>>>(xin, gate0, gates, FDIM);
    k_sort<<<16, 1024, 65536>>>(gates, ord);
    k_greedy<<<1, 1024>>>(ord, perm, gates, scl);
    k_gemm_f32<<<dim3(24, 4, 16), 256>>>(xin, w0, perm, scl, big, TI3, FDIM, FDIM, 0);
    k_triple_norm<<<8192, 256>>>(big, tn1);

    // ---- causal conv ----
    k_w1t<<<dim3(96, 32), dim3(32, 8)>>>(w1, w1t);
    k_gemm_f32<<<dim3(24, 64, 1), 256>>>(tn1, w1t, nullptr, nullptr, big, TI3, TI3, IDIM, 1);
    k_triple_norm<<<8192, 256>>>(big, tn2);

    // ---- MoE 2 ----
    k_logits<<<512, 256>>>(tn2, gate2, gates, IDIM);
    k_sort<<<16, 1024, 65536>>>(gates, ord);
    k_greedy<<<1, 1024>>>(ord, perm, gates, scl);
    k_gemm_f32<<<dim3(4, 4, 16), 256>>>(tn2, w2, perm, scl, y2, FDIM, IDIM, IDIM, 0);

    k_transpose_out<<<dim3(64, 16, 4), dim3(32, 8)>>>(y2, out);
}

// round 17
// speedup vs baseline: 1.9719x; 1.0062x over previous
#include <cuda_runtime.h>
#include <cstdint>

#define NTOK   8192
#define NEXP   16
#define CAP    512
#define FDIM   512
#define IDIM   1024
#define TI3    3072
#define SEQ    2048

#define OFF_XIN   0u
#define OFF_BIG   4194304u
#define OFF_TN1   29360128u
#define OFF_TN2   37748736u
#define OFF_Y2    46137344u
#define OFF_GATES 50331648u
#define OFF_SCALE 50462720u
#define OFF_W1T   50470912u
#define SCRATCH_FLOATS 59908096u

__device__ float g_scratch[SCRATCH_FLOATS];
__device__ int   g_iscr[131072 + 8192];   // ord | perm

__device__ __forceinline__ uint32_t s2u(const void* p) {
    uint32_t r;
    asm("{ .reg .u64 t; cvta.to.shared.u64 t, %1; cvt.u32.u64 %0, t; }" : "=r"(r) : "l"(p));
    return r;
}
__device__ __forceinline__ void cpasync16(uint32_t dst, const void* src) {
    asm volatile("cp.async.cg.shared.global [%0], [%1], 16;" :: "r"(dst), "l"(src));
}
#define CP_COMMIT() asm volatile("cp.async.commit_group;" ::: "memory")
#define CP_WAIT0()  asm volatile("cp.async.wait_group 0;" ::: "memory")

// packed fp32 helpers
__device__ __forceinline__ unsigned long long pk2(float lo, float hi) {
    unsigned long long r;
    asm("mov.b64 %0, {%1, %2};" : "=l"(r) : "f"(lo), "f"(hi));
    return r;
}
__device__ __forceinline__ void upk2(unsigned long long v, float& lo, float& hi) {
    asm("mov.b64 {%0, %1}, %2;" : "=f"(lo), "=f"(hi) : "l"(v));
}
__device__ __forceinline__ void fma2(unsigned long long& d, unsigned long long a,
                                     unsigned long long b) {
    asm("fma.rn.f32x2 %0, %1, %2, %0;" : "+l"(d) : "l"(a), "l"(b));
}

// ---------------- transposes ----------------
__global__ void k_transpose_in(const float* __restrict__ in, float* __restrict__ out) {
    __shared__ float tile[32][33];
    int b = blockIdx.z, s0 = blockIdx.x * 32, f0 = blockIdx.y * 32;
    int tx = threadIdx.x, ty = threadIdx.y;
    #pragma unroll
    for (int r = ty; r < 32; r += 8)
        tile[r][tx] = in[((size_t)(b * FDIM + f0 + r)) * SEQ + s0 + tx];
    __syncthreads();
    #pragma unroll
    for (int r = ty; r < 32; r += 8)
        out[((size_t)(b * SEQ + s0 + r)) * FDIM + f0 + tx] = tile[tx][r];
}

__global__ void k_transpose_out(const float* __restrict__ y2, float* __restrict__ out) {
    __shared__ float tile[32][33];
    int b = blockIdx.z, s0 = blockIdx.x * 32, f0 = blockIdx.y * 32;
    int tx = threadIdx.x, ty = threadIdx.y;
    #pragma unroll
    for (int r = ty; r < 32; r += 8)
        tile[r][tx] = y2[((size_t)(b * SEQ + s0 + r)) * FDIM + f0 + tx];
    __syncthreads();
    #pragma unroll
    for (int r = ty; r < 32; r += 8)
        out[((size_t)(b * FDIM + f0 + r)) * SEQ + s0 + tx] = tile[tx][r];
}

// w1 [O][I][k] -> w1t [k*1024+i][o], single pass over w1
__global__ void k_w1t(const float* __restrict__ w1, float* __restrict__ w1t) {
    __shared__ float tile[3][32][33];
    int o0 = blockIdx.x * 32, i0 = blockIdx.y * 32;
    int tx = threadIdx.x, ty = threadIdx.y;
    #pragma unroll
    for (int r = ty; r < 32; r += 8) {
        const float* src = w1 + ((size_t)(o0 + r) * IDIM + i0 + tx) * 3;
        tile[0][r][tx] = src[0];
        tile[1][r][tx] = src[1];
        tile[2][r][tx] = src[2];
    }
    __syncthreads();
    #pragma unroll
    for (int k = 0; k < 3; k++)
        #pragma unroll
        for (int r = ty; r < 32; r += 8)
            w1t[((size_t)k * IDIM + i0 + r) * TI3 + o0 + tx] = tile[k][tx][r];
}

// ---------------- gate logits + softmax (summation order MUST stay fixed) ----------------
__global__ __launch_bounds__(256) void k_logits(const float* __restrict__ X,
                                                const float* __restrict__ G,
                                                float* __restrict__ gates, int K) {
    __shared__ float Xs[16][65];
    __shared__ float Gs[64][16];
    int t0 = blockIdx.x * 16, tid = threadIdx.x;
    int e = tid & 15, tl = tid >> 4;
    float acc = 0.f;
    for (int k0 = 0; k0 < K; k0 += 64) {
        __syncthreads();
        #pragma unroll
        for (int r = 0; r < 4; r++) {
            int j = tid + 256 * r;
            Xs[j >> 6][j & 63] = X[(size_t)(t0 + (j >> 6)) * K + k0 + (j & 63)];
        }
        #pragma unroll
        for (int r = 0; r < 4; r++) {
            int j = tid + 256 * r;
            Gs[j >> 4][j & 15] = G[(size_t)(k0 + (j >> 4)) * NEXP + (j & 15)];
        }
        __syncthreads();
        #pragma unroll
        for (int k = 0; k < 64; k++) acc += Xs[tl][k] * Gs[k][e];
    }
    float m = acc;
    #pragma unroll
    for (int o = 8; o >= 1; o >>= 1) m = fmaxf(m, __shfl_xor_sync(0xffffffffu, m, o, 16));
    float ex = expf(acc - m);
    float s = ex;
    #pragma unroll
    for (int o = 8; o >= 1; o >>= 1) s += __shfl_xor_sync(0xffffffffu, s, o, 16);
    gates[(size_t)(t0 + tl) * NEXP + e] = ex / s;
}

// ---------------- per-expert descending sort: hybrid register/smem bitonic ----------------
// keys unique -> any correct sort yields the identical ord as before.
#define PHYS(i) ((i) + ((i) >> 3))
#define SORT_SMEM (9216 * 8)

#define CASR(r, j, k)                                                        \
    { bool d = (((base + (r)) & (k)) == 0);                                  \
      unsigned long long a = v[r], b = v[(r) | (j)];                         \
      if ((a < b) == d) { v[r] = b; v[(r) | (j)] = a; } }
#define RPJ1(k) { CASR(0,1,k) CASR(2,1,k) CASR(4,1,k) CASR(6,1,k) }
#define RPJ2(k) { CASR(0,2,k) CASR(1,2,k) CASR(4,2,k) CASR(5,2,k) }
#define RPJ4(k) { CASR(0,4,k) CASR(1,4,k) CASR(2,4,k) CASR(3,4,k) }

__global__ __launch_bounds__(1024) void k_sort(const float* __restrict__ gates,
                                               int* __restrict__ ord) {
    extern __shared__ unsigned long long sm64[];
    int e = blockIdx.x, tid = threadIdx.x;
    int base = tid * 8;
    unsigned long long v[8];
    #pragma unroll
    for (int r = 0; r < 8; r++) {
        int i = base + r;
        unsigned fb = __float_as_uint(gates[(size_t)i * NEXP + e]);
        v[r] = ((unsigned long long)fb << 32) | (unsigned)(NTOK - 1 - i);
    }
    // k = 2, 4, 8 fully in-register
    RPJ1(2)
    RPJ2(4) RPJ1(4)
    RPJ4(8) RPJ2(8) RPJ1(8)
    #pragma unroll
    for (int r = 0; r < 8; r++) sm64[PHYS(base + r)] = v[r];
    __syncthreads();

    for (int k = 16; k <= NTOK; k <<= 1) {
        for (int j = k >> 1; j >= 8; j >>= 1) {
            if (!(tid & (j >> 3))) {      // whole chunk is the low side of its pairs
                #pragma unroll
                for (int r = 0; r < 8; r++) {
                    int i = base + r, l = i ^ j;
                    unsigned long long a = sm64[PHYS(i)], b = sm64[PHYS(l)];
                    bool d = ((i & k) == 0);
                    if ((a < b) == d) { sm64[PHYS(i)] = b; sm64[PHYS(l)] = a; }
                }
            }
            __syncthreads();
        }
        // register tail j = 4, 2, 1
        #pragma unroll
        for (int r = 0; r < 8; r++) v[r] = sm64[PHYS(base + r)];
        RPJ4(k) RPJ2(k) RPJ1(k)
        if (k < NTOK) {
            #pragma unroll
            for (int r = 0; r < 8; r++) sm64[PHYS(base + r)] = v[r];
            __syncthreads();
        }
    }
    #pragma unroll
    for (int r = 0; r < 8; r++) {
        int i = base + r;
        ord[e * NTOK + i] = NTOK - 1 - (int)(unsigned)(v[r] & 0xffffffffu);
    }
}

// ---------------- greedy capacity assignment + fused gate-scale ----------------
__global__ __launch_bounds__(1024) void k_greedy(const int* __restrict__ ord,
                                                 int* __restrict__ perm,
                                                 const float* __restrict__ gates,
                                                 float* __restrict__ scl) {
    __shared__ unsigned assigned[NTOK / 32];
    __shared__ int wsums[32];
    int tid = threadIdx.x, lane = tid & 31, wid = tid >> 5;
    if (tid < NTOK / 32) assigned[tid] = 0u;
    __syncthreads();
    for (int e = 0; e < NEXP; e++) {
        int toks[8];
        int flags = 0, cnt = 0;
        #pragma unroll
        for (int i = 0; i < 8; i++) {
            int tok = ord[e * NTOK + tid * 8 + i];
            toks[i] = tok;
            bool freetok = !((assigned[tok >> 5] >> (tok & 31)) & 1u);
            flags |= ((int)freetok) << i;
            cnt += (int)freetok;
        }
        int v = cnt;
        #pragma unroll
        for (int o = 1; o < 32; o <<= 1) {
            int n = __shfl_up_sync(0xffffffffu, v, o);
            if (lane >= o) v += n;
        }
        if (lane == 31) wsums[wid] = v;
        __syncthreads();
        if (wid == 0) {
            int w = wsums[lane];
            #pragma unroll
            for (int o = 1; o < 32; o <<= 1) {
                int n = __shfl_up_sync(0xffffffffu, w, o);
                if (lane >= o) w += n;
            }
            wsums[lane] = w;
        }
        __syncthreads();
        int r = v - cnt + (wid ? wsums[wid - 1] : 0);
        #pragma unroll
        for (int i = 0; i < 8; i++) {
            if ((flags >> i) & 1) {
                if (r < CAP) {
                    int tok = toks[i];
                    perm[r * NEXP + e] = tok;
                    atomicOr(&assigned[tok >> 5], 1u << (tok & 31));
                }
                r++;
            }
        }
        __syncthreads();
    }
    #pragma unroll
    for (int r = 0; r < 8; r++) {
        int p = r * 1024 + tid;
        int tok = perm[p];
        scl[tok] = gates[(size_t)tok * NEXP + (p >> 9)];
    }
}

// ===== fp32 GEMM, f32x2; fused token-gather + gate-scale in the A path =====
#define KC 16
__global__ __launch_bounds__(256, 2) void k_gemm_f32(
    const float* __restrict__ A, const float* __restrict__ B,
    const int* __restrict__ perm, const float* __restrict__ scl,
    float* __restrict__ Y, int N, int K, int aStride, int isConv)
{
    __shared__ float As[2][KC][128];
    __shared__ float Bs[2][KC][128];
    __shared__ int   stok[128];
    __shared__ float ssc[128];

    int tid = threadIdx.x;
    int e = blockIdx.z, n0 = blockIdx.x * 128, by = blockIdx.y;
    int m0 = isConv ? by * 128 : e * CAP + by * 128;
    if (tid < 128) {
        int tok = perm ? perm[(by * 128 + tid) * NEXP + e] : (m0 + tid);
        stok[tid] = tok;
        ssc[tid]  = perm ? scl[tok] : 1.f;
    }
    __syncthreads();

    const float* Bb = B + (size_t)e * K * N;
    int tx = tid & 15, ty = tid >> 4;
    int rowA = tid >> 2, seg = (tid & 3) * 4;
    int bK = tid >> 4, bC = (tid & 15) * 8;
    uint32_t bs = s2u(&Bs[0][0][0]);

    int tokA0 = 0, tokA1 = 0;
    float sA0 = 1.f, sA1 = 1.f;
    if (!isConv) {
        tokA0 = stok[rowA];      sA0 = ssc[rowA];
        tokA1 = stok[64 + rowA]; sA1 = ssc[64 + rowA];
    }

    unsigned long long acc2[4][8];
    #pragma unroll
    for (int i = 0; i < 4; i++)
        #pragma unroll
        for (int j = 0; j < 8; j++) acc2[i][j] = 0ull;

    float4 ra0, ra1;
    int L = K / KC;

    #define LOADA(c) do {                                                              \
        int kc = (c) * KC;                                                             \
        if (!isConv) {                                                                 \
            ra0 = *(const float4*)(A + (size_t)tokA0 * aStride + kc + seg);            \
            ra1 = *(const float4*)(A + (size_t)tokA1 * aStride + kc + seg);            \
            ra0.x *= sA0; ra0.y *= sA0; ra0.z *= sA0; ra0.w *= sA0;                    \
            ra1.x *= sA1; ra1.y *= sA1; ra1.z *= sA1; ra1.w *= sA1;                    \
        } else {                                                                       \
            int tap = kc >> 10, ca = (kc & 1023) + seg;                                \
            int rg0 = m0 + rowA, rg1 = m0 + 64 + rowA;                                 \
            ra0 = make_float4(0.f, 0.f, 0.f, 0.f);                                     \
            ra1 = make_float4(0.f, 0.f, 0.f, 0.f);                                     \
            if (((rg0 & (SEQ - 1)) + tap) >= 2)                                        \
                ra0 = *(const float4*)(A + (size_t)(rg0 + tap - 2) * aStride + ca);    \
            if (((rg1 & (SEQ - 1)) + tap) >= 2)                                        \
                ra1 = *(const float4*)(A + (size_t)(rg1 + tap - 2) * aStride + ca);    \
        } } while (0)
    #define CPB(c, s) do {                                                             \
        const float* src = Bb + (size_t)((c) * KC + bK) * N + n0 + bC;                 \
        uint32_t dst = bs + ((((s) * KC + bK) * 128 + bC) << 2);                       \
        cpasync16(dst, src);                                                           \
        cpasync16(dst + 16, src + 4);                                                  \
        CP_COMMIT(); } while (0)
    #define STSA(s) do {                                                               \
        As[s][seg + 0][rowA] = ra0.x; As[s][seg + 1][rowA] = ra0.y;                    \
        As[s][seg + 2][rowA] = ra0.z; As[s][seg + 3][rowA] = ra0.w;                    \
        As[s][seg + 0][64 + rowA] = ra1.x; As[s][seg + 1][64 + rowA] = ra1.y;          \
        As[s][seg + 2][64 + rowA] = ra1.z; As[s][seg + 3][64 + rowA] = ra1.w;          \
    } while (0)

    LOADA(0); CPB(0, 0);
    STSA(0); CP_WAIT0(); __syncthreads();

    for (int c = 0; c < L; c++) {
        int s = c & 1;
        if (c + 1 < L) { LOADA(c + 1); CPB(c + 1, s ^ 1); }
        #pragma unroll
        for (int k = 0; k < KC; k++) {
            unsigned long long au[4];
            float bq[8];
            *(float4*)&au[0] = *(const float4*)&As[s][k][ty * 4];
            *(float4*)&au[2] = *(const float4*)&As[s][k][64 + ty * 4];
            *(float4*)&bq[0] = *(const float4*)&Bs[s][k][tx * 4];
            *(float4*)&bq[4] = *(const float4*)&Bs[s][k][64 + tx * 4];
            unsigned long long bd[8];
            #pragma unroll
            for (int j = 0; j < 8; j++) bd[j] = pk2(bq[j], bq[j]);
            #pragma unroll
            for (int i = 0; i < 4; i++)
                #pragma unroll
                for (int j = 0; j < 8; j++) fma2(acc2[i][j], au[i], bd[j]);
        }
        if (c + 1 < L) { STSA(s ^ 1); CP_WAIT0(); __syncthreads(); }
    }

    #pragma unroll
    for (int i = 0; i < 8; i++) {
        int r = (i < 4) ? (ty * 4 + i) : (64 + ty * 4 + i - 4);
        int tok = stok[r];
        float* yr = Y + (size_t)tok * N + n0;
        float v[8];
        #pragma unroll
        for (int j = 0; j < 8; j++) {
            float lo, hi;
            upk2(acc2[i >> 1][j], lo, hi);
            v[j] = (i & 1) ? hi : lo;
        }
        *(float4*)(yr + tx * 4)      = make_float4(v[0], v[1], v[2], v[3]);
        *(float4*)(yr + 64 + tx * 4) = make_float4(v[4], v[5], v[6], v[7]);
    }
}

// ---------------- triple norm ----------------
__global__ __launch_bounds__(256) void k_triple_norm(const float* __restrict__ Y,
                                                     float* __restrict__ Z) {
    __shared__ float sm[8];
    int t = blockIdx.x, tid = threadIdx.x;
    const float* row = Y + (size_t)t * TI3;
    float v[4];
    float ls = 0.f;
    #pragma unroll
    for (int i = 0; i < 4; i++) {
        int c = tid + 256 * i;
        float r = fmaxf(row[c], 0.f);
        v[i] = r * r * r * row[IDIM + c] + row[2 * IDIM + c];
        ls += v[i];
    }
    #pragma unroll
    for (int o = 16; o >= 1; o >>= 1) ls += __shfl_xor_sync(0xffffffffu, ls, o);
    if ((tid & 31) == 0) sm[tid >> 5] = ls;
    __syncthreads();
    float mean = (sm[0] + sm[1] + sm[2] + sm[3] + sm[4] + sm[5] + sm[6] + sm[7]) * (1.0f / 1024.0f);
    __syncthreads();
    float ss = 0.f;
    #pragma unroll
    for (int i = 0; i < 4; i++) { float d = v[i] - mean; ss += d * d; }
    #pragma unroll
    for (int o = 16; o >= 1; o >>= 1) ss += __shfl_xor_sync(0xffffffffu, ss, o);
    if ((tid & 31) == 0) sm[tid >> 5] = ss;
    __syncthreads();
    float tot = sm[0] + sm[1] + sm[2] + sm[3] + sm[4] + sm[5] + sm[6] + sm[7];
    float rstd = sqrtf(1024.0f / tot);
    #pragma unroll
    for (int i = 0; i < 4; i++)
        Z[(size_t)t * IDIM + tid + 256 * i] = (v[i] - mean) * rstd;
}

// ---------------- host ----------------
extern "C" void kernel_launch(void* const* d_in, const int* in_sizes, int n_in,
                              void* d_out, int out_size) {
    const float* inp   = (const float*)d_in[0];
    const float* w0    = (const float*)d_in[1];
    const float* gate0 = (const float*)d_in[2];
    const float* w1    = (const float*)d_in[3];
    const float* w2    = (const float*)d_in[4];
    const float* gate2 = (const float*)d_in[5];
    float* out = (float*)d_out;

    void* p;  cudaGetSymbolAddress(&p, g_scratch);
    void* pi; cudaGetSymbolAddress(&pi, g_iscr);
    float* fs = (float*)p;
    int*   is = (int*)pi;

    float* xin   = fs + OFF_XIN;
    float* big   = fs + OFF_BIG;
    float* tn1   = fs + OFF_TN1;
    float* tn2   = fs + OFF_TN2;
    float* y2    = fs + OFF_Y2;
    float* gates = fs + OFF_GATES;
    float* scl   = fs + OFF_SCALE;
    float* w1t   = fs + OFF_W1T;
    int* ord  = is;
    int* perm = is + 131072;

    cudaFuncSetAttribute(k_sort, cudaFuncAttributeMaxDynamicSharedMemorySize, SORT_SMEM);

    // ---- MoE 1 ----
    k_transpose_in<<<dim3(64, 16, 4), dim3(32, 8)>>>(inp, xin);
    k_logits<<<512, 256>>>(xin, gate0, gates, FDIM);
    k_sort<<<16, 1024, SORT_SMEM>>>(gates, ord);
    k_greedy<<<1, 1024>>>(ord, perm, gates, scl);
    k_gemm_f32<<<dim3(24, 4, 16), 256>>>(xin, w0, perm, scl, big, TI3, FDIM, FDIM, 0);
    k_triple_norm<<<8192, 256>>>(big, tn1);

    // ---- causal conv ----
    k_w1t<<<dim3(96, 32), dim3(32, 8)>>>(w1, w1t);
    k_gemm_f32<<<dim3(24, 64, 1), 256>>>(tn1, w1t, nullptr, nullptr, big, TI3, TI3, IDIM, 1);
    k_triple_norm<<<8192, 256>>>(big, tn2);

    // ---- MoE 2 ----
    k_logits<<<512, 256>>>(tn2, gate2, gates, IDIM);
    k_sort<<<16, 1024, SORT_SMEM>>>(gates, ord);
    k_greedy<<<1, 1024>>>(ord, perm, gates, scl);
    k_gemm_f32<<<dim3(4, 4, 16), 256>>>(tn2, w2, perm, scl, y2, FDIM, IDIM, IDIM, 0);

    k_transpose_out<<<dim3(64, 16, 4), dim3(32, 8)>>>(y2, out);
}